// round 1
// baseline (speedup 1.0000x reference)
#include <cuda_runtime.h>
#include <cuda_bf16.h>

// Problem constants (fixed-shape problem: N=2000 nodes, F=2, HIDDEN=64, K=3, G=256 graphs)
#define NN    2000
#define EMAX  20000
#define HID   64
#define TPB   512

// ---------------- device-global scratch (no allocs allowed) ----------------
__device__ float g_degw[NN];        // weighted in-degree (segment_sum(ew, col))
__device__ int   g_cnt[NN];         // edge count per destination
__device__ int   g_ptr[NN + 1];     // CSR row pointers (by destination)
__device__ int   g_cur[NN];         // scatter cursors
__device__ short g_src[EMAX];       // CSR: source node of each edge
__device__ float g_w[EMAX];         // CSR: gcn_norm weight of each edge

// ---------------- prepass kernels ----------------
__global__ void k_zero() {
    int i = blockIdx.x * blockDim.x + threadIdx.x;
    if (i < NN) { g_degw[i] = 0.f; g_cnt[i] = 0; }
}

__global__ void k_deg(const int* __restrict__ col, const float* __restrict__ ew, int E) {
    int i = blockIdx.x * blockDim.x + threadIdx.x;
    if (i < E) {
        int c = col[i];
        atomicAdd(&g_degw[c], ew[i]);
        atomicAdd(&g_cnt[c], 1);
    }
}

// single-block exclusive scan of g_cnt[0..NN) -> g_ptr, g_cur ; g_ptr[NN]=E
__global__ void k_scan(int E) {
    __shared__ int warpsum[32];
    int t = threadIdx.x;                 // 1024 threads, 2 elements each
    int i0 = 2 * t, i1 = 2 * t + 1;
    int a0 = (i0 < NN) ? g_cnt[i0] : 0;
    int a1 = (i1 < NN) ? g_cnt[i1] : 0;
    int tot = a0 + a1;
    int lane = t & 31, wid = t >> 5;
    int v = tot;
    #pragma unroll
    for (int o = 1; o < 32; o <<= 1) {
        int u = __shfl_up_sync(0xFFFFFFFFu, v, o);
        if (lane >= o) v += u;
    }
    if (lane == 31) warpsum[wid] = v;
    __syncthreads();
    if (wid == 0) {
        int w = warpsum[lane];
        #pragma unroll
        for (int o = 1; o < 32; o <<= 1) {
            int u = __shfl_up_sync(0xFFFFFFFFu, w, o);
            if (lane >= o) w += u;
        }
        warpsum[lane] = w;
    }
    __syncthreads();
    int base = v - tot + (wid ? warpsum[wid - 1] : 0);   // exclusive prefix for this thread
    if (i0 < NN) { g_ptr[i0] = base;      g_cur[i0] = base; }
    if (i1 < NN) { g_ptr[i1] = base + a0; g_cur[i1] = base + a0; }
    if (t == 0)  g_ptr[NN] = E;
}

__global__ void k_scatter(const int* __restrict__ row, const int* __restrict__ col,
                          const float* __restrict__ ew, int E) {
    int i = blockIdx.x * blockDim.x + threadIdx.x;
    if (i < E) {
        int r = row[i], c = col[i];
        float dr = g_degw[r], dc = g_degw[c];
        float ir = (dr > 0.f) ? rsqrtf(dr) : 0.f;
        float ic = (dc > 0.f) ? rsqrtf(dc) : 0.f;
        float nrm = ir * ew[i] * ic;
        int p = atomicAdd(&g_cur[c], 1);
        g_src[p] = (short)r;
        g_w[p]   = nrm;
    }
}

// ---------------- main fused kernel: one CTA per graph ----------------
// smem layout (floats):
//   pbuf[4][NN] float2 | scratch[NN] float2 | xbuf[NN] float2
//   w1t[64][8] | w2s[64][8] | b1s[64] | sptr[NN+1] (int)
#define SMEM_F2   (6 * NN)                 // float2 count
#define SMEM_FLT  (SMEM_F2 * 2 + 512 + 512 + 64)
#define SMEM_BYTES (SMEM_FLT * 4 + (NN + 4) * 4)

__device__ __forceinline__ void gather_hop(const float2* __restrict__ pin,
                                           float2* __restrict__ pout,
                                           const float2* __restrict__ addbuf,
                                           const int* __restrict__ sptr,
                                           int t, int bs) {
    for (int n = t; n < NN; n += bs) {
        int b = sptr[n], e = sptr[n + 1];
        float ax = 0.f, ay = 0.f;
        if (addbuf) { float2 a = addbuf[n]; ax = a.x; ay = a.y; }
        for (int q = b; q < e; q++) {
            float w  = g_w[q];
            int   s  = g_src[q];
            float2 v = pin[s];
            ax = fmaf(v.x, w, ax);
            ay = fmaf(v.y, w, ay);
        }
        pout[n] = make_float2(ax, ay);
    }
}

__global__ __launch_bounds__(TPB)
void k_main(const float* __restrict__ x,
            const float* __restrict__ W1, const float* __restrict__ b1,
            const float* __restrict__ W2, const float* __restrict__ b2,
            float* __restrict__ out) {
    extern __shared__ float sm[];
    float2* pbuf0   = (float2*)sm;
    float2* pbuf1   = pbuf0 + NN;
    float2* pbuf2   = pbuf1 + NN;
    float2* pbuf3   = pbuf2 + NN;
    float2* scratch = pbuf3 + NN;
    float2* xbuf    = scratch + NN;
    float*  w1t = (float*)(xbuf + NN);     // [64][8] : w1t[j*8+i] = W1cat[i][j]
    float*  w2s = w1t + 512;               // [64][8] : w2s[j*8+c] = W2[k][j][o], c=k*2+o
    float*  b1s = w2s + 512;
    int*    sptr = (int*)(b1s + 64);

    const int t  = threadIdx.x;
    const int bs = blockDim.x;
    const int g  = blockIdx.x;

    // stage weights
    for (int i = t; i < 512; i += bs) {
        int j = i >> 3, c = i & 7;
        w1t[i] = W1[c * HID + j];                       // W1 row-major [8][64]
        w2s[i] = W2[(c >> 1) * (HID * 2) + j * 2 + (c & 1)];
    }
    for (int i = t; i < HID; i += bs) b1s[i] = b1[i];
    for (int i = t; i < NN + 1; i += bs) sptr[i] = g_ptr[i];

    // stage x (node features are contiguous pairs)
    const float2* xg = (const float2*)(x + (size_t)g * 2 * NN);
    for (int n = t; n < NN; n += bs) { float2 v = xg[n]; xbuf[n] = v; pbuf0[n] = v; }
    __syncthreads();

    // layer-1 hops: p_k = A p_{k-1}   (F=2)
    gather_hop(pbuf0, pbuf1, nullptr, sptr, t, bs); __syncthreads();
    gather_hop(pbuf1, pbuf2, nullptr, sptr, t, bs); __syncthreads();
    gather_hop(pbuf2, pbuf3, nullptr, sptr, t, bs); __syncthreads();

    // dense per-node: [8] -> 64 (relu) -> [8]; overwrite pbuf rows in place with m_k
    const float4* w1t4 = (const float4*)w1t;
    const float4* w2s4 = (const float4*)w2s;
    for (int n = t; n < NN; n += bs) {
        float2 a0 = pbuf0[n], a1 = pbuf1[n], a2 = pbuf2[n], a3 = pbuf3[n];
        float pr[8] = {a0.x, a0.y, a1.x, a1.y, a2.x, a2.y, a3.x, a3.y};
        float m[8]  = {0, 0, 0, 0, 0, 0, 0, 0};
        #pragma unroll 8
        for (int j = 0; j < HID; j++) {
            float4 wa = w1t4[2 * j], wb = w1t4[2 * j + 1];
            float h = b1s[j];
            h = fmaf(pr[0], wa.x, h); h = fmaf(pr[1], wa.y, h);
            h = fmaf(pr[2], wa.z, h); h = fmaf(pr[3], wa.w, h);
            h = fmaf(pr[4], wb.x, h); h = fmaf(pr[5], wb.y, h);
            h = fmaf(pr[6], wb.z, h); h = fmaf(pr[7], wb.w, h);
            h = fmaxf(h, 0.f);
            float4 va = w2s4[2 * j], vb = w2s4[2 * j + 1];
            m[0] = fmaf(h, va.x, m[0]); m[1] = fmaf(h, va.y, m[1]);
            m[2] = fmaf(h, va.z, m[2]); m[3] = fmaf(h, va.w, m[3]);
            m[4] = fmaf(h, vb.x, m[4]); m[5] = fmaf(h, vb.y, m[5]);
            m[6] = fmaf(h, vb.z, m[6]); m[7] = fmaf(h, vb.w, m[7]);
        }
        pbuf0[n] = make_float2(m[0], m[1]);   // m0
        pbuf1[n] = make_float2(m[2], m[3]);   // m1
        pbuf2[n] = make_float2(m[4], m[5]);   // m2
        pbuf3[n] = make_float2(m[6], m[7]);   // m3
    }
    __syncthreads();

    // layer-2 Horner: out2 = m0 + A(m1 + A(m2 + A m3))
    gather_hop(pbuf3, scratch, pbuf2, sptr, t, bs); __syncthreads();  // s = m2 + A m3
    gather_hop(scratch, pbuf3, pbuf1, sptr, t, bs); __syncthreads();  // s = m1 + A s

    // final: out = x + m0 + A s + b2
    float b20 = b2[0], b21 = b2[1];
    float2* og = (float2*)out + (size_t)g * NN;
    for (int n = t; n < NN; n += bs) {
        int b = sptr[n], e = sptr[n + 1];
        float2 acc = pbuf0[n];
        for (int q = b; q < e; q++) {
            float w  = g_w[q];
            int   s  = g_src[q];
            float2 v = pbuf3[s];
            acc.x = fmaf(v.x, w, acc.x);
            acc.y = fmaf(v.y, w, acc.y);
        }
        float2 xv = xbuf[n];
        og[n] = make_float2(xv.x + acc.x + b20, xv.y + acc.y + b21);
    }
}

// ---------------- launcher ----------------
extern "C" void kernel_launch(void* const* d_in, const int* in_sizes, int n_in,
                              void* d_out, int out_size) {
    const float* x   = (const float*)d_in[0];
    const int*   row = (const int*)  d_in[1];
    const int*   col = (const int*)  d_in[2];
    const float* ew  = (const float*)d_in[3];
    const float* W1  = (const float*)d_in[4];
    const float* b1  = (const float*)d_in[5];
    const float* W2  = (const float*)d_in[6];
    const float* b2  = (const float*)d_in[7];

    const int E = in_sizes[1];
    const int G = in_sizes[0] / (2 * NN);

    cudaFuncSetAttribute(k_main, cudaFuncAttributeMaxDynamicSharedMemorySize, SMEM_BYTES);

    k_zero<<<(NN + 255) / 256, 256>>>();
    k_deg<<<(E + 255) / 256, 256>>>(col, ew, E);
    k_scan<<<1, 1024>>>(E);
    k_scatter<<<(E + 255) / 256, 256>>>(row, col, ew, E);
    k_main<<<G, TPB, SMEM_BYTES>>>(x, W1, b1, W2, b2, (float*)d_out);
}